// round 5
// baseline (speedup 1.0000x reference)
#include <cuda_runtime.h>

// TokenEmbedding segment-sum, two-phase:
//   Phase A: scatter packed segment bounds  seg2[b][t] = (start[t], start[t+1])
//            (thread per wordpiece w: writes .x of tokens in (prev,cur] and
//             .y of the preceding token -> one 8B load gives both bounds)
//   Phase B: one CTA per (b, t), 64 threads; each thread owns FOUR float4
//            columns (c, c+64, c+128, c+192) -> 4 unconditional independent
//            loads per row -> ~2x bytes-in-flight vs 2-col split.

#define B_DIM 8
#define L_DIM 4096
#define H_DIM 1024
#define H4 (H_DIM / 4)     // 256 float4 per row
#define TB  64             // phase-B threads: each covers 4 float4 columns

// packed bounds: seg2[b][t] = { start[t], start[t+1] }
__device__ int2 g_seg2[B_DIM][L_DIM];

__global__ __launch_bounds__(256) void seg_bounds_kernel(
    const int* __restrict__ w2t)      // [B, L] sorted per row
{
    const int b = blockIdx.y;
    const int w = blockIdx.x * blockDim.x + threadIdx.x;
    if (w >= L_DIM) return;

    const int* idx = w2t + (size_t)b * L_DIM;
    const int cur  = __ldg(idx + w);
    const int prev = (w > 0) ? __ldg(idx + w - 1) : -1;

    // start[t] = w for every token t in (prev, cur]
    for (int t = prev + 1; t <= cur; ++t) {
        g_seg2[b][t].x = w;              // lo of token t
        if (t >= 1) g_seg2[b][t - 1].y = w;  // hi of token t-1
    }

    // tail: start[t] = L for t in (cur, L]
    if (w == L_DIM - 1) {
        for (int t = cur + 1; t <= L_DIM; ++t) {
            if (t < L_DIM) g_seg2[b][t].x = L_DIM;
            g_seg2[b][t - 1].y = L_DIM;
        }
    }
}

__global__ __launch_bounds__(TB) void token_segsum_kernel(
    const float* __restrict__ x,      // [B, L, H]
    float*       __restrict__ out)    // [B, L, H]
{
    const int t = blockIdx.x;   // token id
    const int b = blockIdx.y;   // batch

    // single 8B broadcast metadata load (L2-hot)
    const int2 bnd = __ldg(&g_seg2[b][t]);
    const int lo = bnd.x;
    const int hi = bnd.y;

    const int c = threadIdx.x;  // float4 column 0..63 (owns +64, +128, +192)
    const float4* __restrict__ rows =
        reinterpret_cast<const float4*>(x + (size_t)b * L_DIM * H_DIM);

    float4 a0 = make_float4(0.f, 0.f, 0.f, 0.f);
    float4 a1 = a0, a2 = a0, a3 = a0;

    for (int w = lo; w < hi; ++w) {
        const float4* r = rows + (size_t)w * H4;
        float4 v0 = __ldcs(r + c);
        float4 v1 = __ldcs(r + c + TB);
        float4 v2 = __ldcs(r + c + 2 * TB);
        float4 v3 = __ldcs(r + c + 3 * TB);
        a0.x += v0.x; a0.y += v0.y; a0.z += v0.z; a0.w += v0.w;
        a1.x += v1.x; a1.y += v1.y; a1.z += v1.z; a1.w += v1.w;
        a2.x += v2.x; a2.y += v2.y; a2.z += v2.z; a2.w += v2.w;
        a3.x += v3.x; a3.y += v3.y; a3.z += v3.z; a3.w += v3.w;
    }

    float4* __restrict__ orow =
        reinterpret_cast<float4*>(out + ((size_t)b * L_DIM + t) * H_DIM);
    __stcs(orow + c,          a0);
    __stcs(orow + c + TB,     a1);
    __stcs(orow + c + 2 * TB, a2);
    __stcs(orow + c + 3 * TB, a3);
}

extern "C" void kernel_launch(void* const* d_in, const int* in_sizes, int n_in,
                              void* d_out, int out_size)
{
    const float* x   = (const float*)d_in[0];   // sequence_output [B,L,H] fp32
    const int*   w2t = (const int*)  d_in[1];   // wordpiece_to_token [B,L] int32
    float*       out = (float*)d_out;           // [B,L,H] fp32

    dim3 gridA(L_DIM / 256, B_DIM);
    seg_bounds_kernel<<<gridA, 256>>>(w2t);

    dim3 gridB(L_DIM, B_DIM);
    token_segsum_kernel<<<gridB, TB>>>(x, out);
}